// round 1
// baseline (speedup 1.0000x reference)
#include <cuda_runtime.h>
#include <math.h>

// MMDDistance: x,y (4096,256) fp32 -> scalar fp32.
//
// Pipeline (all graph-capturable, allocation-free, deterministic):
//  P1a k_rowsq : per-row squared norms sq[i], partial sums of sq
//  P1b k_colsum: partial column sums of T (for analytic sum(L2))
//  P1c k_bw    : bandwidth = (2n*sum(sq) - 2*|colsum|^2)/(n^2-n)/4
//                store c = log2(e)/(16*bw)
//  P2  k_main  : fused triangle GEMM (G tiles of T*T^T) + kernel-sum epilogue
//  P3  k_final : deterministic final reduction -> d_out[0]

#define NROWS 8192
#define NX    4096
#define DDIM  256
#define TB    128
#define KT    16
#define NTILE 64            // NROWS / TB
#define SQPAD 132           // padded shared stride

__device__ float  g_sq[NROWS];
__device__ double g_p_sqsum[1024];
__device__ double g_p_col[64][DDIM];
__device__ float  g_negc;                  // -log2(e)/(16*bandwidth)
__device__ double g_partial[NTILE * NTILE];

// ---------------------------------------------------------------------------
// P1a: one warp per row. sq[row] = sum_k t[row][k]^2 ; block partial of sq.
__global__ __launch_bounds__(256) void k_rowsq(const float* __restrict__ x,
                                               const float* __restrict__ y) {
    int warp = threadIdx.x >> 5, lane = threadIdx.x & 31;
    int row = blockIdx.x * 8 + warp;
    const float* p = (row < NX) ? (x + (size_t)row * DDIM)
                                : (y + (size_t)(row - NX) * DDIM);
    float s = 0.f;
#pragma unroll
    for (int k = lane; k < DDIM; k += 32) { float v = p[k]; s = fmaf(v, v, s); }
#pragma unroll
    for (int off = 16; off; off >>= 1) s += __shfl_down_sync(0xffffffffu, s, off);
    __shared__ double ws[8];
    if (lane == 0) { g_sq[row] = s; ws[warp] = (double)s; }
    __syncthreads();
    if (threadIdx.x == 0) {
        double t = 0.0;
#pragma unroll
        for (int i = 0; i < 8; i++) t += ws[i];
        g_p_sqsum[blockIdx.x] = t;
    }
}

// ---------------------------------------------------------------------------
// P1b: block b sums columns over rows [128b, 128b+128). Thread k owns column k.
__global__ __launch_bounds__(256) void k_colsum(const float* __restrict__ x,
                                                const float* __restrict__ y) {
    int k = threadIdx.x;
    int r0 = blockIdx.x * 128;
    double acc = 0.0;
    for (int i = 0; i < 128; i++) {
        int row = r0 + i;
        const float* p = (row < NX) ? (x + (size_t)row * DDIM)
                                    : (y + (size_t)(row - NX) * DDIM);
        acc += (double)p[k];
    }
    g_p_col[blockIdx.x][k] = acc;
}

// ---------------------------------------------------------------------------
// P1c: finalize bandwidth. sum(L2) = 2n*sum(sq) - 2*|colsum|^2.
__global__ __launch_bounds__(256) void k_bw() {
    int t = threadIdx.x;
    __shared__ double red[256];
    __shared__ double colsq_sh;

    double s = 0.0;
    for (int b = 0; b < 64; b++) s += g_p_col[b][t];
    red[t] = s * s;
    __syncthreads();
    for (int off = 128; off; off >>= 1) {
        if (t < off) red[t] += red[t + off];
        __syncthreads();
    }
    if (t == 0) colsq_sh = red[0];
    __syncthreads();

    double q = 0.0;
    for (int b = t; b < 1024; b += 256) q += g_p_sqsum[b];
    red[t] = q;
    __syncthreads();
    for (int off = 128; off; off >>= 1) {
        if (t < off) red[t] += red[t + off];
        __syncthreads();
    }
    if (t == 0) {
        double sumsq = red[0];
        double n = (double)NROWS;
        double sumL2 = 2.0 * n * sumsq - 2.0 * colsq_sh;
        double bw = sumL2 / (n * n - n) / 4.0;  // / KERNEL_MUL^(KERNEL_NUM//2)
        g_negc = (float)(-M_LOG2E / (16.0 * bw));
    }
}

// ---------------------------------------------------------------------------
// P2: fused GEMM + MMD epilogue on block-upper-triangle tiles.
// 256 threads as 16x16; each thread owns an 8x8 microtile of the 128x128 tile.
__global__ __launch_bounds__(256, 2) void k_main(const float* __restrict__ x,
                                                 const float* __restrict__ y) {
    const int bj = blockIdx.x;  // column tile
    const int bi = blockIdx.y;  // row tile
    const int slot = bi * NTILE + bj;
    if (bj < bi) {              // lower triangle: contribute zero (determinism)
        if (threadIdx.x == 0) g_partial[slot] = 0.0;
        return;
    }

    __shared__ float As[KT][SQPAD];
    __shared__ float Bs[KT][SQPAD];
    __shared__ float sqA[TB], sqB[TB];
    __shared__ double red[256];

    const int t  = threadIdx.x;
    const int tx = t & 15;
    const int ty = t >> 4;

    // tile bases: each 128-row tile lies fully in x (bi<32) or y (bi>=32)
    const float* Abase = (bi < 32) ? (x + (size_t)bi * TB * DDIM)
                                   : (y + (size_t)(bi - 32) * TB * DDIM);
    const float* Bbase = (bj < 32) ? (x + (size_t)bj * TB * DDIM)
                                   : (y + (size_t)(bj - 32) * TB * DDIM);

    if (t < TB)       sqA[t]       = g_sq[bi * TB + t];
    else              sqB[t - TB]  = g_sq[bj * TB + (t - TB)];

    float acc[8][8];
#pragma unroll
    for (int i = 0; i < 8; i++)
#pragma unroll
        for (int j = 0; j < 8; j++) acc[i][j] = 0.f;

    for (int kt = 0; kt < DDIM; kt += KT) {
        // stage 128x16 of A and B (transposed into [k][row])
#pragma unroll
        for (int l = t; l < TB * KT; l += 256) {
            int r  = l >> 4;
            int kk = l & 15;
            As[kk][r] = Abase[(size_t)r * DDIM + kt + kk];
            Bs[kk][r] = Bbase[(size_t)r * DDIM + kt + kk];
        }
        __syncthreads();

#pragma unroll
        for (int k = 0; k < KT; k++) {
            float4 a0 = *(const float4*)&As[k][ty * 8];
            float4 a1 = *(const float4*)&As[k][ty * 8 + 4];
            float4 b0 = *(const float4*)&Bs[k][tx * 8];
            float4 b1 = *(const float4*)&Bs[k][tx * 8 + 4];
            float a[8] = {a0.x, a0.y, a0.z, a0.w, a1.x, a1.y, a1.z, a1.w};
            float b[8] = {b0.x, b0.y, b0.z, b0.w, b1.x, b1.y, b1.z, b1.w};
#pragma unroll
            for (int i = 0; i < 8; i++)
#pragma unroll
                for (int j = 0; j < 8; j++)
                    acc[i][j] = fmaf(a[i], b[j], acc[i][j]);
        }
        __syncthreads();
    }

    // epilogue: L2 -> sum of 5 Gaussian kernels via one EX2 + 4 squarings
    const float negc = g_negc;
    double dacc = 0.0;
#pragma unroll
    for (int i = 0; i < 8; i++) {
        float si = sqA[ty * 8 + i];
#pragma unroll
        for (int j = 0; j < 8; j++) {
            float L2 = fmaxf(si + sqB[tx * 8 + j] - 2.f * acc[i][j], 0.f);
            float v;
            asm("ex2.approx.ftz.f32 %0, %1;" : "=f"(v) : "f"(L2 * negc));
            float v2 = v * v, v4 = v2 * v2, v8 = v4 * v4, v16 = v8 * v8;
            dacc += (double)(v + v2 + v4 + v8 + v16);
        }
    }

    // sign is uniform per tile (tiles never straddle the x/y boundary)
    double sgnw = ((bi < 32) == (bj < 32)) ? 1.0 : -1.0;
    if (bj != bi) sgnw *= 2.0;  // symmetry weight for strictly-upper tiles
    dacc *= sgnw;

    red[t] = dacc;
    __syncthreads();
    for (int off = 128; off; off >>= 1) {
        if (t < off) red[t] += red[t + off];
        __syncthreads();
    }
    if (t == 0) g_partial[slot] = red[0];
}

// ---------------------------------------------------------------------------
// P3: deterministic final reduction -> mean over 4096^2.
__global__ __launch_bounds__(256) void k_final(float* __restrict__ out) {
    int t = threadIdx.x;
    double s = 0.0;
    for (int i = t; i < NTILE * NTILE; i += 256) s += g_partial[i];
    __shared__ double red[256];
    red[t] = s;
    __syncthreads();
    for (int off = 128; off; off >>= 1) {
        if (t < off) red[t] += red[t + off];
        __syncthreads();
    }
    if (t == 0) out[0] = (float)(red[0] / ((double)NX * (double)NX));
}

// ---------------------------------------------------------------------------
extern "C" void kernel_launch(void* const* d_in, const int* in_sizes, int n_in,
                              void* d_out, int out_size) {
    const float* x = (const float*)d_in[0];
    const float* y = (const float*)d_in[1];
    (void)in_sizes; (void)n_in; (void)out_size;

    k_rowsq<<<1024, 256>>>(x, y);
    k_colsum<<<64, 256>>>(x, y);
    k_bw<<<1, 256>>>();
    dim3 grid(NTILE, NTILE);
    k_main<<<grid, 256>>>(x, y);
    k_final<<<1, 256>>>((float*)d_out);
}

// round 6
// speedup vs baseline: 2.6282x; 2.6282x over previous
#include <cuda_runtime.h>
#include <cuda_bf16.h>
#include <cstdint>
#include <math.h>

// MMDDistance on GB300 (sm_103 base target): split-bf16 3-pass HMMA gram
// (mma.sync m16n8k16 bf16 -> fp32) + fused 5-kernel MMD epilogue.
//
//  k_stats : per-row squared norms + per-block column sums + sq partials
//  k_bw    : bandwidth via analytic sum(L2) = 2n*sum(sq) - 2*|colsum|^2
//  k_main  : one 128x128 upper-triangle tile per CTA; stage fp32->(hi,lo)bf16
//            in padded smem; per k16 step ldmatrix + 3 mma passes per (m,n)
//            block; epilogue L2 -> one EX2 + 4 squarings -> signed partials
//  k_final : deterministic reduction -> mean

#define NROWS 8192
#define NX    4096
#define DDIM  256
#define TB    128
#define NTILE 64
#define NWORK (NTILE * (NTILE + 1) / 2)   // 2080 upper-triangle tiles
#define CHUNK 64
#define NCHUNK (DDIM / CHUNK)
#define SPITCH 72                          // bf16 elements per smem row (padded)

__device__ float  g_sq[NROWS];
__device__ double g_p_sqsum[256];
__device__ float  g_p_colf[256][DDIM];
__device__ float  g_negc;                  // -log2(e)/(16*bandwidth)
__device__ double g_partial[NWORK];

// ---------------------------------------------------------------- helpers
__device__ __forceinline__ uint32_t smem_addr_u32(const void* p) {
    uint32_t a;
    asm("{ .reg .u64 t; cvta.to.shared.u64 t, %1; cvt.u32.u64 %0, t; }"
        : "=r"(a) : "l"(p));
    return a;
}
__device__ __forceinline__ void ldsm4(uint32_t addr, uint32_t r[4]) {
    asm volatile("ldmatrix.sync.aligned.m8n8.x4.shared.b16 {%0,%1,%2,%3}, [%4];"
                 : "=r"(r[0]), "=r"(r[1]), "=r"(r[2]), "=r"(r[3]) : "r"(addr));
}
__device__ __forceinline__ void mma16816(float d[4], const uint32_t a[4],
                                         uint32_t b0, uint32_t b1) {
    asm volatile(
        "mma.sync.aligned.m16n8k16.row.col.f32.bf16.bf16.f32 "
        "{%0,%1,%2,%3}, {%4,%5,%6,%7}, {%8,%9}, {%0,%1,%2,%3};"
        : "+f"(d[0]), "+f"(d[1]), "+f"(d[2]), "+f"(d[3])
        : "r"(a[0]), "r"(a[1]), "r"(a[2]), "r"(a[3]), "r"(b0), "r"(b1));
}
// ldmatrix x4 address: lanes 0-15 -> rows row0..row0+15 at col k0,
// lanes 16-31 -> same rows at col k0+8 (both A m16k16 and B n16k16 cases).
__device__ __forceinline__ uint32_t lm_addr(uint32_t base, int row0, int k0,
                                            int lane) {
    int r = row0 + (lane & 15);
    int c = k0 + ((lane >> 4) << 3);
    return base + (uint32_t)(r * SPITCH + c) * 2u;
}

// ---------------------------------------------------------------------------
// k_stats: 256 blocks x 256 thr; block b covers rows [32b, 32b+32).
__global__ __launch_bounds__(256) void k_stats(const float* __restrict__ x,
                                               const float* __restrict__ y) {
    const int b = blockIdx.x, r0 = b * 32;
    const int w = threadIdx.x >> 5, lane = threadIdx.x & 31;
    __shared__ double ws[8];

    const float* base = (r0 < NX) ? (x + (size_t)r0 * DDIM)
                                  : (y + (size_t)(r0 - NX) * DDIM);
    double wsum = 0.0;
#pragma unroll
    for (int rr = 0; rr < 4; rr++) {
        int r = w * 4 + rr;
        const float* p = base + (size_t)r * DDIM;
        float s = 0.f;
#pragma unroll
        for (int k = lane; k < DDIM; k += 32) { float v = p[k]; s = fmaf(v, v, s); }
#pragma unroll
        for (int off = 16; off; off >>= 1) s += __shfl_down_sync(0xffffffffu, s, off);
        if (lane == 0) { g_sq[r0 + r] = s; wsum += (double)s; }
    }
    if (lane == 0) ws[w] = wsum;

    int k = threadIdx.x;
    float acc = 0.f;
#pragma unroll 8
    for (int i = 0; i < 32; i++) acc += base[(size_t)i * DDIM + k];
    g_p_colf[b][k] = acc;

    __syncthreads();
    if (threadIdx.x == 0) {
        double t = 0.0;
#pragma unroll
        for (int i = 0; i < 8; i++) t += ws[i];
        g_p_sqsum[b] = t;
    }
}

// ---------------------------------------------------------------------------
__global__ __launch_bounds__(256) void k_bw() {
    int t = threadIdx.x;
    __shared__ double red[256];
    __shared__ double colsq_sh;

    float cs = 0.f;
#pragma unroll 8
    for (int b = 0; b < 256; b++) cs += g_p_colf[b][t];
    red[t] = (double)cs * (double)cs;
    __syncthreads();
    for (int off = 128; off; off >>= 1) {
        if (t < off) red[t] += red[t + off];
        __syncthreads();
    }
    if (t == 0) colsq_sh = red[0];
    __syncthreads();

    red[t] = g_p_sqsum[t];
    __syncthreads();
    for (int off = 128; off; off >>= 1) {
        if (t < off) red[t] += red[t + off];
        __syncthreads();
    }
    if (t == 0) {
        double n = (double)NROWS;
        double sumL2 = 2.0 * n * red[0] - 2.0 * colsq_sh;
        double bw = sumL2 / (n * n - n) / 4.0;   // / KERNEL_MUL^(KERNEL_NUM//2)
        g_negc = (float)(-M_LOG2E / (16.0 * bw));
    }
}

// ---------------------------------------------------------------------------
// k_main: 2080 CTAs, one upper-triangle 128x128 tile each.
__global__ __launch_bounds__(256, 2) void k_main(const float* __restrict__ x,
                                                 const float* __restrict__ y) {
    // triangular index -> (bi, bj), bj >= bi. offset(bi) = bi*NTILE - bi(bi-1)/2
    const int u = blockIdx.x;
    int bi = (int)((2.0f * NTILE + 1.0f
                    - sqrtf((2.0f * NTILE + 1.0f) * (2.0f * NTILE + 1.0f)
                            - 8.0f * (float)u)) * 0.5f);
    while (bi > 0 && bi * NTILE - bi * (bi - 1) / 2 > u) bi--;
    while ((bi + 1) * NTILE - (bi + 1) * bi / 2 <= u) bi++;
    const int bj = bi + (u - (bi * NTILE - bi * (bi - 1) / 2));

    extern __shared__ __align__(16) char dsm[];
    __shared__ float  sqA[TB], sqB[TB];
    __shared__ double red[256];

    const int t    = threadIdx.x;
    const int lane = t & 31;
    const int w    = t >> 5;
    const int wr   = w & 3;          // warp row block  (32 rows)
    const int wc   = w >> 2;         // warp col block  (64 cols)

    // 4 bf16 tiles [128][SPITCH]: Ahi, Alo, Bhi, Blo
    const uint32_t sbase = smem_addr_u32(dsm);
    const uint32_t TILEB = TB * SPITCH * 2;   // 18432 B
    const uint32_t uAhi = sbase, uAlo = sbase + TILEB,
                   uBhi = sbase + 2 * TILEB, uBlo = sbase + 3 * TILEB;
    char* tAhi = dsm;
    char* tAlo = dsm + TILEB;
    char* tBhi = dsm + 2 * TILEB;
    char* tBlo = dsm + 3 * TILEB;

    if (t < TB)      sqA[t]      = g_sq[bi * TB + t];
    else             sqB[t - TB] = g_sq[bj * TB + (t - TB)];

    const float* Abase = (bi < 32) ? (x + (size_t)bi * TB * DDIM)
                                   : (y + (size_t)(bi - 32) * TB * DDIM);
    const float* Bbase = (bj < 32) ? (x + (size_t)bj * TB * DDIM)
                                   : (y + (size_t)(bj - 32) * TB * DDIM);

    float acc[2][8][4];
#pragma unroll
    for (int m = 0; m < 2; m++)
#pragma unroll
        for (int n = 0; n < 8; n++)
#pragma unroll
            for (int q = 0; q < 4; q++) acc[m][n][q] = 0.f;

    const int k4 = t & 15;     // float4 index within the 64-wide chunk
    const int rb = t >> 4;     // staging row base (16 rows per sweep)

    for (int c = 0; c < NCHUNK; c++) {
        const int kt = c * CHUNK;
        __syncthreads();       // protect smem from previous chunk's readers
        // ---- stage A and B chunks: fp32 -> (hi, lo) bf16, padded layout ----
#pragma unroll
        for (int mm = 0; mm < 2; mm++) {
            const float* src = mm ? Bbase : Abase;
            char* dhi = mm ? tBhi : tAhi;
            char* dlo = mm ? tBlo : tAlo;
#pragma unroll
            for (int it = 0; it < 8; it++) {
                int r = rb + it * 16;
                float4 v = *(const float4*)(src + (size_t)r * DDIM + kt + k4 * 4);
                __nv_bfloat16 h0 = __float2bfloat16_rn(v.x);
                __nv_bfloat16 h1 = __float2bfloat16_rn(v.y);
                __nv_bfloat16 h2 = __float2bfloat16_rn(v.z);
                __nv_bfloat16 h3 = __float2bfloat16_rn(v.w);
                float l0 = v.x - __bfloat162float(h0);
                float l1 = v.y - __bfloat162float(h1);
                float l2 = v.z - __bfloat162float(h2);
                float l3 = v.w - __bfloat162float(h3);
                uint32_t hi01 = (uint32_t)__bfloat16_as_ushort(h0)
                              | ((uint32_t)__bfloat16_as_ushort(h1) << 16);
                uint32_t hi23 = (uint32_t)__bfloat16_as_ushort(h2)
                              | ((uint32_t)__bfloat16_as_ushort(h3) << 16);
                uint32_t lo01 = (uint32_t)__bfloat16_as_ushort(__float2bfloat16_rn(l0))
                              | ((uint32_t)__bfloat16_as_ushort(__float2bfloat16_rn(l1)) << 16);
                uint32_t lo23 = (uint32_t)__bfloat16_as_ushort(__float2bfloat16_rn(l2))
                              | ((uint32_t)__bfloat16_as_ushort(__float2bfloat16_rn(l3)) << 16);
                uint32_t off = ((uint32_t)r * SPITCH + (uint32_t)k4 * 4) * 2;
                *(uint2*)(dhi + off) = make_uint2(hi01, hi23);
                *(uint2*)(dlo + off) = make_uint2(lo01, lo23);
            }
        }
        __syncthreads();

        // ---- MMA over this chunk: 4 k16 steps ----
#pragma unroll
        for (int ks = 0; ks < CHUNK / 16; ks++) {
            const int k0 = ks * 16;
            uint32_t ah[2][4], al[2][4];
#pragma unroll
            for (int m = 0; m < 2; m++) {
                int row0 = wr * 32 + m * 16;
                ldsm4(lm_addr(uAhi, row0, k0, lane), ah[m]);
                ldsm4(lm_addr(uAlo, row0, k0, lane), al[m]);
            }
#pragma unroll
            for (int h = 0; h < 2; h++) {      // column halves of 32
                uint32_t bh[2][4], bl[2][4];
#pragma unroll
                for (int s = 0; s < 2; s++) {  // two n16 blocks
                    int n0 = wc * 64 + h * 32 + s * 16;
                    ldsm4(lm_addr(uBhi, n0, k0, lane), bh[s]);
                    ldsm4(lm_addr(uBlo, n0, k0, lane), bl[s]);
                }
#pragma unroll
                for (int m = 0; m < 2; m++)
#pragma unroll
                    for (int s = 0; s < 2; s++)
#pragma unroll
                        for (int sub = 0; sub < 2; sub++) {
                            const int nb = h * 4 + s * 2 + sub;
                            // ldsm4 regs: {m0,m1,m2,m3} = {n0-7 k0, n8-15 k0,
                            //  n0-7 k8, n8-15 k8}; b-frag (n8,k16) = {rA, rB}
                            uint32_t b0 = bh[s][sub];       // k0-7
                            uint32_t b1 = bh[s][sub + 2];   // k8-15
                            mma16816(acc[m][nb], ah[m], b0, b1);
                            b0 = bl[s][sub]; b1 = bl[s][sub + 2];
                            mma16816(acc[m][nb], ah[m], b0, b1);  // hi*lo
                            b0 = bh[s][sub]; b1 = bh[s][sub + 2];
                            mma16816(acc[m][nb], al[m], b0, b1);  // lo*hi
                        }
            }
        }
    }

    // ---- epilogue: 5-kernel sum per pair ----
    const float negc = g_negc;
    const int g  = lane >> 2;
    const int c2 = (lane & 3) * 2;
    float fsum = 0.f;
#pragma unroll
    for (int m = 0; m < 2; m++) {
        const int r0 = wr * 32 + m * 16 + g;
        const float s0 = sqA[r0], s1 = sqA[r0 + 8];
#pragma unroll
        for (int nb = 0; nb < 8; nb++) {
            const int cc = wc * 64 + nb * 8 + c2;
            const float t0 = sqB[cc], t1 = sqB[cc + 1];
#pragma unroll
            for (int q = 0; q < 4; q++) {
                const float sr = (q >= 2) ? s1 : s0;
                const float sc = (q & 1) ? t1 : t0;
                float L2 = fmaxf(sr + sc - 2.f * acc[m][nb][q], 0.f);
                float v;
                asm("ex2.approx.ftz.f32 %0, %1;" : "=f"(v) : "f"(L2 * negc));
                float v2 = v * v, v4 = v2 * v2, v8 = v4 * v4, v16 = v8 * v8;
                fsum += v + v2 + v4 + v8 + v16;
            }
        }
    }
    double sgnw = ((bi < 32) == (bj < 32)) ? 1.0 : -1.0;
    if (bj != bi) sgnw *= 2.0;
    red[t] = (double)fsum * sgnw;
    __syncthreads();
    for (int off = 128; off; off >>= 1) {
        if (t < off) red[t] += red[t + off];
        __syncthreads();
    }
    if (t == 0) g_partial[u] = red[0];
}

// ---------------------------------------------------------------------------
__global__ __launch_bounds__(256) void k_final(float* __restrict__ out) {
    int t = threadIdx.x;
    double s = 0.0;
    for (int i = t; i < NWORK; i += 256) s += g_partial[i];
    __shared__ double red[256];
    red[t] = s;
    __syncthreads();
    for (int off = 128; off; off >>= 1) {
        if (t < off) red[t] += red[t + off];
        __syncthreads();
    }
    if (t == 0) out[0] = (float)(red[0] / ((double)NX * (double)NX));
}

// ---------------------------------------------------------------------------
#define SMEM_DYN (4 * TB * SPITCH * 2)   // 73728 B

extern "C" void kernel_launch(void* const* d_in, const int* in_sizes, int n_in,
                              void* d_out, int out_size) {
    const float* x = (const float*)d_in[0];
    const float* y = (const float*)d_in[1];
    (void)in_sizes; (void)n_in; (void)out_size;

    k_stats<<<256, 256>>>(x, y);
    k_bw<<<1, 256>>>();
    cudaFuncSetAttribute(k_main, cudaFuncAttributeMaxDynamicSharedMemorySize, SMEM_DYN);
    k_main<<<NWORK, 256, SMEM_DYN>>>(x, y);
    k_final<<<1, 256>>>((float*)d_out);
}

// round 8
// speedup vs baseline: 2.9503x; 1.1226x over previous
#include <cuda_runtime.h>
#include <cuda_bf16.h>
#include <cstdint>
#include <math.h>

// MMDDistance on GB300 (sm_103 base target): split-bf16 3-pass HMMA gram
// with prepacked bf16(hi,lo) operands + cp.async staging + swizzled smem.
//
//  k_prep  : fp32 -> (hi,lo) bf16 prepack into __device__ globals, fused with
//            per-row squared norms, column sums, sq partials
//  k_bw    : bandwidth via analytic sum(L2) = 2n*sum(sq) - 2*|colsum|^2
//  k_main  : one 128x128 upper-triangle tile per CTA; cp.async-stage 4 bf16
//            tiles per 64-chunk (swizzled), ldmatrix + 3 mma passes,
//            epilogue L2 -> one EX2 + 4 squarings -> signed partials
//  k_final : deterministic reduction -> mean

#define NROWS 8192
#define NX    4096
#define DDIM  256
#define TB    128
#define NTILE 64
#define NWORK (NTILE * (NTILE + 1) / 2)   // 2080 upper-triangle tiles
#define CHUNK 64
#define NCHUNK (DDIM / CHUNK)
#define ROWB  128                          // smem row bytes (64 bf16, swizzled)
#define TILEB (TB * ROWB)                  // 16384 B per tile

__device__ __nv_bfloat16 g_hi[NROWS * DDIM];
__device__ __nv_bfloat16 g_lo[NROWS * DDIM];
__device__ float  g_sq[NROWS];
__device__ double g_p_sqsum[256];
__device__ float  g_p_colf[256][DDIM];
__device__ float  g_negc;                  // -log2(e)/(16*bandwidth)
__device__ double g_partial[NWORK];

// ---------------------------------------------------------------- helpers
__device__ __forceinline__ uint32_t smem_addr_u32(const void* p) {
    uint32_t a;
    asm("{ .reg .u64 t; cvta.to.shared.u64 t, %1; cvt.u32.u64 %0, t; }"
        : "=r"(a) : "l"(p));
    return a;
}
__device__ __forceinline__ void ldsm4(uint32_t addr, uint32_t r[4]) {
    asm volatile("ldmatrix.sync.aligned.m8n8.x4.shared.b16 {%0,%1,%2,%3}, [%4];"
                 : "=r"(r[0]), "=r"(r[1]), "=r"(r[2]), "=r"(r[3]) : "r"(addr));
}
__device__ __forceinline__ void mma16816(float d[4], const uint32_t a[4],
                                         uint32_t b0, uint32_t b1) {
    asm volatile(
        "mma.sync.aligned.m16n8k16.row.col.f32.bf16.bf16.f32 "
        "{%0,%1,%2,%3}, {%4,%5,%6,%7}, {%8,%9}, {%0,%1,%2,%3};"
        : "+f"(d[0]), "+f"(d[1]), "+f"(d[2]), "+f"(d[3])
        : "r"(a[0]), "r"(a[1]), "r"(a[2]), "r"(a[3]), "r"(b0), "r"(b1));
}
__device__ __forceinline__ void cpasync16(uint32_t dst, const void* src) {
    asm volatile("cp.async.ca.shared.global [%0], [%1], 16;"
                 :: "r"(dst), "l"(src) : "memory");
}
// swizzled ldmatrix x4 address: logical (row, k) with k multiple of 8.
// smem layout: byte = row*128 + ((unit ^ (row & 7)) << 4), unit = k>>3.
__device__ __forceinline__ uint32_t lm_addr(uint32_t base, int row0, int k0,
                                            int lane) {
    int r = row0 + (lane & 15);
    int u = (k0 >> 3) + (lane >> 4);
    u ^= (r & 7);
    return base + (uint32_t)(r * ROWB + (u << 4));
}

// ---------------------------------------------------------------------------
// k_prep: 256 blocks x 256 thr; block b covers rows [32b, 32b+32).
// Prepacks (hi,lo) bf16, computes column partials, row sq, sq partials.
__global__ __launch_bounds__(256) void k_prep(const float* __restrict__ x,
                                              const float* __restrict__ y) {
    const int b = blockIdx.x, r0 = b * 32;
    const int w = threadIdx.x >> 5, lane = threadIdx.x & 31;
    __shared__ double ws[8];

    const float* base = (r0 < NX) ? (x + (size_t)r0 * DDIM)
                                  : (y + (size_t)(r0 - NX) * DDIM);

    // conversion + column partials: thread owns column k over 32 rows
    {
        const int k = threadIdx.x;
        float acc = 0.f;
#pragma unroll 8
        for (int i = 0; i < 32; i++) {
            float v = base[(size_t)i * DDIM + k];
            __nv_bfloat16 h = __float2bfloat16_rn(v);
            float l = v - __bfloat162float(h);
            size_t idx = (size_t)(r0 + i) * DDIM + k;
            g_hi[idx] = h;
            g_lo[idx] = __float2bfloat16_rn(l);
            acc += v;
        }
        g_p_colf[b][k] = acc;
    }

    // row squared norms: warp handles 4 rows (reads are L1/L2 hot)
    double wsum = 0.0;
#pragma unroll
    for (int rr = 0; rr < 4; rr++) {
        int r = w * 4 + rr;
        const float* p = base + (size_t)r * DDIM;
        float s = 0.f;
#pragma unroll
        for (int k = lane; k < DDIM; k += 32) { float v = p[k]; s = fmaf(v, v, s); }
#pragma unroll
        for (int off = 16; off; off >>= 1) s += __shfl_down_sync(0xffffffffu, s, off);
        if (lane == 0) { g_sq[r0 + r] = s; wsum += (double)s; }
    }
    if (lane == 0) ws[w] = wsum;
    __syncthreads();
    if (threadIdx.x == 0) {
        double t = 0.0;
#pragma unroll
        for (int i = 0; i < 8; i++) t += ws[i];
        g_p_sqsum[b] = t;
    }
}

// ---------------------------------------------------------------------------
__global__ __launch_bounds__(256) void k_bw() {
    int t = threadIdx.x;
    __shared__ double red[256];
    __shared__ double colsq_sh;

    float cs = 0.f;
#pragma unroll 8
    for (int b = 0; b < 256; b++) cs += g_p_colf[b][t];
    red[t] = (double)cs * (double)cs;
    __syncthreads();
    for (int off = 128; off; off >>= 1) {
        if (t < off) red[t] += red[t + off];
        __syncthreads();
    }
    if (t == 0) colsq_sh = red[0];
    __syncthreads();

    red[t] = g_p_sqsum[t];
    __syncthreads();
    for (int off = 128; off; off >>= 1) {
        if (t < off) red[t] += red[t + off];
        __syncthreads();
    }
    if (t == 0) {
        double n = (double)NROWS;
        double sumL2 = 2.0 * n * red[0] - 2.0 * colsq_sh;
        double bw = sumL2 / (n * n - n) / 4.0;   // / KERNEL_MUL^(KERNEL_NUM//2)
        g_negc = (float)(-M_LOG2E / (16.0 * bw));
    }
}

// ---------------------------------------------------------------------------
// k_main: 2080 CTAs, one upper-triangle 128x128 tile each.
__global__ __launch_bounds__(256, 2) void k_main() {
    // triangular index -> (bi, bj), bj >= bi
    const int u = blockIdx.x;
    int bi = (int)((2.0f * NTILE + 1.0f
                    - sqrtf((2.0f * NTILE + 1.0f) * (2.0f * NTILE + 1.0f)
                            - 8.0f * (float)u)) * 0.5f);
    while (bi > 0 && bi * NTILE - bi * (bi - 1) / 2 > u) bi--;
    while ((bi + 1) * NTILE - (bi + 1) * bi / 2 <= u) bi++;
    const int bj = bi + (u - (bi * NTILE - bi * (bi - 1) / 2));

    extern __shared__ __align__(16) char dsm[];
    __shared__ float  sqA[TB], sqB[TB];
    __shared__ double red[256];

    const int t    = threadIdx.x;
    const int lane = t & 31;
    const int w    = t >> 5;
    const int wr   = w & 3;          // warp row block  (32 rows)
    const int wc   = w >> 2;         // warp col block  (64 cols)

    const uint32_t sbase = smem_addr_u32(dsm);
    const uint32_t uT[4] = {sbase, sbase + TILEB, sbase + 2 * TILEB,
                            sbase + 3 * TILEB};   // Ahi, Alo, Bhi, Blo

    if (t < TB)      sqA[t]      = g_sq[bi * TB + t];
    else             sqB[t - TB] = g_sq[bj * TB + (t - TB)];

    const size_t rowA = (size_t)bi * TB * DDIM;
    const size_t rowB = (size_t)bj * TB * DDIM;
    const __nv_bfloat16* srcT[4] = {g_hi + rowA, g_lo + rowA,
                                    g_hi + rowB, g_lo + rowB};

    float acc[2][8][4];
#pragma unroll
    for (int m = 0; m < 2; m++)
#pragma unroll
        for (int n = 0; n < 8; n++)
#pragma unroll
            for (int q = 0; q < 4; q++) acc[m][n][q] = 0.f;

    const int crow = t >> 3;   // 0..31: staging row base
    const int cun  = t & 7;    // 16B unit within 128B row

    for (int c = 0; c < NCHUNK; c++) {
        const int kt = c * CHUNK;
        __syncthreads();       // previous chunk's readers are done
        // ---- stage 4 tiles via cp.async (prepacked bf16, swizzled dst) ----
#pragma unroll
        for (int tl = 0; tl < 4; tl++) {
            const __nv_bfloat16* src = srcT[tl] + kt + cun * 8;
#pragma unroll
            for (int i = 0; i < 4; i++) {
                int r = crow + i * 32;
                uint32_t dst = uT[tl] + (uint32_t)(r * ROWB
                             + ((cun ^ (r & 7)) << 4));
                cpasync16(dst, src + (size_t)r * DDIM);
            }
        }
        asm volatile("cp.async.commit_group;" ::: "memory");
        asm volatile("cp.async.wait_group 0;" ::: "memory");
        __syncthreads();

        // ---- MMA over this chunk: 4 k16 steps ----
#pragma unroll
        for (int ks = 0; ks < CHUNK / 16; ks++) {
            const int k0 = ks * 16;
            uint32_t ah[2][4], al[2][4];
#pragma unroll
            for (int m = 0; m < 2; m++) {
                int row0 = wr * 32 + m * 16;
                ldsm4(lm_addr(uT[0], row0, k0, lane), ah[m]);
                ldsm4(lm_addr(uT[1], row0, k0, lane), al[m]);
            }
#pragma unroll
            for (int h = 0; h < 2; h++) {      // column halves of 32
                uint32_t bh[2][4], bl[2][4];
#pragma unroll
                for (int s = 0; s < 2; s++) {  // two n16 blocks
                    int n0 = wc * 64 + h * 32 + s * 16;
                    ldsm4(lm_addr(uT[2], n0, k0, lane), bh[s]);
                    ldsm4(lm_addr(uT[3], n0, k0, lane), bl[s]);
                }
#pragma unroll
                for (int m = 0; m < 2; m++)
#pragma unroll
                    for (int s = 0; s < 2; s++)
#pragma unroll
                        for (int sub = 0; sub < 2; sub++) {
                            const int nb = h * 4 + s * 2 + sub;
                            uint32_t b0 = bh[s][sub];       // k0-7
                            uint32_t b1 = bh[s][sub + 2];   // k8-15
                            mma16816(acc[m][nb], ah[m], b0, b1);  // hi*hi
                            b0 = bl[s][sub]; b1 = bl[s][sub + 2];
                            mma16816(acc[m][nb], ah[m], b0, b1);  // hi*lo
                            b0 = bh[s][sub]; b1 = bh[s][sub + 2];
                            mma16816(acc[m][nb], al[m], b0, b1);  // lo*hi
                        }
            }
        }
    }

    // ---- epilogue: 5-kernel sum per pair ----
    const float negc = g_negc;
    const int g  = lane >> 2;
    const int c2 = (lane & 3) * 2;
    float fsum = 0.f;
#pragma unroll
    for (int m = 0; m < 2; m++) {
        const int r0 = wr * 32 + m * 16 + g;
        const float s0 = sqA[r0], s1 = sqA[r0 + 8];
#pragma unroll
        for (int nb = 0; nb < 8; nb++) {
            const int cc = wc * 64 + nb * 8 + c2;
            const float t0 = sqB[cc], t1 = sqB[cc + 1];
#pragma unroll
            for (int q = 0; q < 4; q++) {
                const float sr = (q >= 2) ? s1 : s0;
                const float sc = (q & 1) ? t1 : t0;
                float L2 = fmaxf(sr + sc - 2.f * acc[m][nb][q], 0.f);
                float v;
                asm("ex2.approx.ftz.f32 %0, %1;" : "=f"(v) : "f"(L2 * negc));
                float v2 = v * v, v4 = v2 * v2, v8 = v4 * v4, v16 = v8 * v8;
                fsum += v + v2 + v4 + v8 + v16;
            }
        }
    }
    double sgnw = ((bi < 32) == (bj < 32)) ? 1.0 : -1.0;
    if (bj != bi) sgnw *= 2.0;
    red[t] = (double)fsum * sgnw;
    __syncthreads();
    for (int off = 128; off; off >>= 1) {
        if (t < off) red[t] += red[t + off];
        __syncthreads();
    }
    if (t == 0) g_partial[u] = red[0];
}

// ---------------------------------------------------------------------------
__global__ __launch_bounds__(256) void k_final(float* __restrict__ out) {
    int t = threadIdx.x;
    double s = 0.0;
    for (int i = t; i < NWORK; i += 256) s += g_partial[i];
    __shared__ double red[256];
    red[t] = s;
    __syncthreads();
    for (int off = 128; off; off >>= 1) {
        if (t < off) red[t] += red[t + off];
        __syncthreads();
    }
    if (t == 0) out[0] = (float)(red[0] / ((double)NX * (double)NX));
}

// ---------------------------------------------------------------------------
#define SMEM_DYN (4 * TILEB)   // 65536 B -> 2 CTAs/SM

extern "C" void kernel_launch(void* const* d_in, const int* in_sizes, int n_in,
                              void* d_out, int out_size) {
    const float* x = (const float*)d_in[0];
    const float* y = (const float*)d_in[1];
    (void)in_sizes; (void)n_in; (void)out_size;

    k_prep<<<256, 256>>>(x, y);
    k_bw<<<1, 256>>>();
    cudaFuncSetAttribute(k_main, cudaFuncAttributeMaxDynamicSharedMemorySize, SMEM_DYN);
    k_main<<<NWORK, 256, SMEM_DYN>>>();
    k_final<<<1, 256>>>((float*)d_out);
}